// round 15
// baseline (speedup 1.0000x reference)
#include <cuda_runtime.h>
#include <cstdint>
#include <math.h>

#define NT     16
#define S_LEN  4096
#define B_SZ   512
#define HALF   (S_LEN / 2)                 // 2048 iterations
#define CHUNK  8
#define NBLK   (B_SZ / 2)                  // 256 blocks, 2 rows each

typedef unsigned long long u64;

// Per-row partial results + completion counter (device globals: legal scratch).
__device__ float g_fwd[B_SZ];
__device__ float g_gold[B_SZ];
__device__ unsigned g_done = 0;

// ---- smem helpers ----
__device__ __forceinline__ unsigned smem_addr(const void* p) {
    unsigned a;
    asm("{ .reg .u64 t; cvta.to.shared.u64 t, %1; cvt.u32.u64 %0, t; }"
        : "=r"(a) : "l"(p));
    return a;
}
__device__ __forceinline__ void sts64(unsigned addr, float a, float b) {
    asm volatile("st.shared.v2.f32 [%0], {%1, %2};" :: "r"(addr), "f"(a), "f"(b));
}
__device__ __forceinline__ void lds4(unsigned a, u64* p) {
    asm volatile("ld.shared.v2.b64 {%0,%1}, [%2];" : "=l"(p[0]), "=l"(p[1]) : "r"(a));
    asm volatile("ld.shared.v2.b64 {%0,%1}, [%2];" : "=l"(p[2]), "=l"(p[3]) : "r"(a + 16));
    asm volatile("ld.shared.v2.b64 {%0,%1}, [%2];" : "=l"(p[4]), "=l"(p[5]) : "r"(a + 32));
    asm volatile("ld.shared.v2.b64 {%0,%1}, [%2];" : "=l"(p[6]), "=l"(p[7]) : "r"(a + 48));
}

// ---- packed fp32x2 math ----
__device__ __forceinline__ u64 mul2(u64 a, u64 b) {
    u64 d; asm("mul.rn.f32x2 %0, %1, %2;" : "=l"(d) : "l"(a), "l"(b)); return d;
}
__device__ __forceinline__ u64 fma2(u64 a, u64 b, u64 c) {
    u64 d; asm("fma.rn.f32x2 %0, %1, %2, %3;" : "=l"(d) : "l"(a), "l"(b), "l"(c)); return d;
}
__device__ __forceinline__ u64 add2(u64 a, u64 b) {
    u64 d; asm("add.rn.f32x2 %0, %1, %2;" : "=l"(d) : "l"(a), "l"(b)); return d;
}
__device__ __forceinline__ u64 pack2(float lo, float hi) {
    u64 d; asm("mov.b64 %0, {%1, %2};" : "=l"(d) : "f"(lo), "f"(hi)); return d;
}
__device__ __forceinline__ void unpack2(u64 v, float& lo, float& hi) {
    asm("mov.b64 {%0, %1}, %2;" : "=f"(lo), "=f"(hi) : "l"(v));
}

__device__ __forceinline__ float dot16(const u64* v, const u64* c) {
    u64 p0 = mul2(v[0], c[0]);
    u64 p1 = mul2(v[1], c[1]);
    u64 p2 = mul2(v[2], c[2]);
    u64 p3 = mul2(v[3], c[3]);
    p0 = fma2(v[4], c[4], p0);
    p1 = fma2(v[5], c[5], p1);
    p2 = fma2(v[6], c[6], p2);
    p3 = fma2(v[7], c[7], p3);
    const u64 q0 = add2(p0, p1);
    const u64 q1 = add2(p2, p3);
    const u64 qq = add2(q0, q1);
    float lo, hi;
    unpack2(qq, lo, hi);
    return lo + hi;
}

// Detect element strides (bytes) of tags/mask buffers (JAX dtype ambiguity).
__device__ __forceinline__ int detect_mask_stride(const unsigned char* mb) {
    return (mb[1] | mb[2] | mb[3]) ? 1 : 4;
}
__device__ __forceinline__ int detect_tag_stride(const void* tp) {
    const int* w = (const int*)tp;
    int nz = 0;
#pragma unroll
    for (int k = 0; k < 32; ++k) nz |= w[1 + 2 * k];
    return nz ? 4 : 8;
}

// Gold path score for one row, one full warp (32 lanes).
__device__ __forceinline__ void gold_row(
    int row, const unsigned char* tags_b, int tstride,
    const unsigned char* mask_b, int mstride,
    const float* emissions, const float* start_t, const float* end_t,
    const float* transitions, int lane)
{
    const unsigned char* trow = tags_b + (size_t)row * S_LEN * tstride;
    const unsigned char* mrow = mask_b + (size_t)row * S_LEN * mstride;
    const float*         erow = emissions + (size_t)row * S_LEN * NT;

    float acc = 0.0f;
    int   cnt = 0;
    for (int t = lane; t < S_LEN; t += 32) {
        const int tg = trow[(size_t)t * tstride];
        const int mm = mrow[(size_t)t * mstride];
        cnt += mm ? 1 : 0;
        if (t == 0) {
            acc += start_t[tg] + erow[tg];
        } else if (mm) {
            const int tpv = trow[(size_t)(t - 1) * tstride];
            acc += transitions[tpv * NT + tg] + erow[(size_t)t * NT + tg];
        }
    }
#pragma unroll
    for (int off = 16; off >= 1; off >>= 1) {
        acc += __shfl_xor_sync(0xffffffffu, acc, off);
        cnt += __shfl_xor_sync(0xffffffffu, cnt, off);
    }
    if (lane == 0) {
        int last = cnt - 1;
        if (last < 0) last = 0;
        const int lt = trow[(size_t)last * tstride];
        g_gold[row] = acc + end_t[lt];
    }
}

// One block = 64 threads = 2 warps, 2 batch rows.
//   Phase 1 (warp 0 only; warp 1 sleeps at the barrier — zero issue pressure):
//     bidirectional scan, 4 streams of 8 lanes:
//     q = lane>>3: dir = q>>1, r = q&1; lane owns components (2h, 2h+1).
//     fwd: alpha_t = w_t.(E^T alpha_{t-1});  bwd (delta): d_t = (E d_{t+1}).w_t
//   Phase 2 (both warps): gold path score, one row per warp.
__global__ void __launch_bounds__(64, 1) crf_fused_kernel(
    const float* __restrict__ emissions,          // [B, S, NT] f32
    const void*  __restrict__ tags_raw,           // [B, S] i32 or i64
    const void*  __restrict__ mask_raw,           // [B, S] u8 or i32 (bool)
    const float* __restrict__ transitions,        // [NT, NT] f32
    const float* __restrict__ start_t,            // [NT] f32
    const float* __restrict__ end_t,              // [NT] f32
    float* __restrict__ out)
{
    const int warp = threadIdx.x >> 5;
    const int lane = threadIdx.x & 31;

    const unsigned char* mask_b = (const unsigned char*)mask_raw;
    const unsigned char* tags_b = (const unsigned char*)tags_raw;
    const int mstride = detect_mask_stride(mask_b);
    const int tstride = detect_tag_stride(tags_raw);

    // ping-pong state: [parity][stream(4)][tag(16)] floats  (warp-0 private)
    __shared__ float sbuf[2][4][NT];
    __shared__ int   s_last;

    if (warp == 0) {
        const int q   = lane >> 3;                // stream id
        const int dir = q >> 1;                   // 0 fwd, 1 bwd
        const int r   = q & 1;                    // row within block
        const int h   = lane & 7;                 // owns tags 2h, 2h+1
        const int j0  = 2 * h, j1 = 2 * h + 1;
        const int row = blockIdx.x * 2 + r;

        // dot constants: fwd = columns j0/j1 of expT; bwd = rows j0/j1.
        u64 Ca[8], Cb[8];
#pragma unroll
        for (int i = 0; i < 8; ++i) {
            const int a0 = dir ? (j0 * NT + 2 * i)     : ((2 * i) * NT + j0);
            const int a1 = dir ? (j0 * NT + 2 * i + 1) : ((2 * i + 1) * NT + j0);
            const int b0 = dir ? (j1 * NT + 2 * i)     : ((2 * i) * NT + j1);
            const int b1 = dir ? (j1 * NT + 2 * i + 1) : ((2 * i + 1) * NT + j1);
            Ca[i] = pack2(__expf(transitions[a0]), __expf(transitions[a1]));
            Cb[i] = pack2(__expf(transitions[b0]), __expf(transitions[b1]));
        }

        const float2* erow2 =
            reinterpret_cast<const float2*>(emissions + (size_t)row * S_LEN * NT) + h;
        const unsigned char* mrowb = mask_b + (size_t)row * S_LEN * mstride;

        // prologue prefetch. iteration i: fwd e_i, m_i; bwd e_{S-1-i}, m_{S-i}.
        float2 ebuf[CHUNK];
        int    mbuf[CHUNK];
#pragma unroll
        for (int p = 0; p < CHUNK; ++p) {
            const int et = dir ? (S_LEN - 1 - p) : p;
            const int mt = dir ? ((p == 0) ? S_LEN - 1 : S_LEN - p) : p;
            ebuf[p] = erow2[(size_t)et * 8];
            mbuf[p] = mrowb[(size_t)mt * mstride];
        }
        mbuf[0] = 0;                              // iteration 0 = init step

        // steady-state prefetch pointers (pointer-bump only; always in-bounds)
        const int estep = dir ? -8 : 8;           // float2 units per t
        const int mstep = dir ? -mstride : mstride;
        const float2* epf = erow2 + (dir ? (size_t)(S_LEN - 1 - CHUNK) * 8
                                         : (size_t)CHUNK * 8);
        const unsigned char* mpf = mrowb + (dir ? (size_t)(S_LEN - CHUNK) * mstride
                                                : (size_t)CHUNK * mstride);

        // init: fwd alpha_0 = exp(start + e_0); bwd d_{S-1} = exp(end + e_{S-1})
        const float base0 = dir ? end_t[j0] : start_t[j0];
        const float base1 = dir ? end_t[j1] : start_t[j1];
        float s0 = __expf(base0 + ebuf[0].x);
        float s1 = __expf(base1 + ebuf[0].y);
        float2 ep = ebuf[0];
        int    ksum = 0;

        const unsigned sb   = smem_addr(&sbuf[0][0][0]);
        const unsigned base = sb + (unsigned)(q * 64);
        const unsigned hb   = (unsigned)(h * 8);
        unsigned par = 0;                          // parity byte offset (0 / 256)

        sts64(base + hb, s0, s1);                  // publish init (parity 0)

        for (int tb = 0; tb < HALF; tb += CHUNK) {
#pragma unroll
            for (int u = 0; u < CHUNK; ++u) {
                const float2 e = ebuf[u];
                const int    m = mbuf[u];

                // off-chain emission weights (e loaded CHUNK iterations ago)
                const float wx = __expf(e.x);
                const float wy = __expf(e.y);
                const unsigned pbx = __float_as_uint(wx) + 0x3f800000u;
                const unsigned pby = __float_as_uint(wy) + 0x3f800000u;

                // gather own stream's 16-state (4x LDS.128 broadcast)
                u64 v[8];
                lds4(base + par, v);

                // prefetch (always in-bounds within the row)
                ebuf[u] = *epf;  epf += estep;
                mbuf[u] = *mpf;  mpf += mstep;

                // exponent fold: P = w * 2^-k from stream state[0]
                const unsigned ub  = (unsigned)v[0];
                const int kcur = (int)((ub >> 23) & 0xffu) - 127;
                const unsigned msk = ub & 0x7f800000u;
                const float Px = __uint_as_float(pbx - msk);
                const float Py = __uint_as_float(pby - msk);

                // two independent packed trees
                const float accx = dot16(v, Ca);
                const float accy = dot16(v, Cb);

                // HOT path: unconditional update (mask is overwhelmingly true)
                const float os0 = s0, os1 = s1;
                s0    = accx * Px;
                s1    = accy * Py;
                ksum += kcur;

                // COLD fixup: masked step keeps old state
                //   fwd: s unchanged; bwd (delta): s *= exp(e_t - e_{t+1})
                if (!m) {
                    const float Rx = dir ? __expf(e.x - ep.x) : 1.0f;
                    const float Ry = dir ? __expf(e.y - ep.y) : 1.0f;
                    s0 = os0 * Rx;
                    s1 = os1 * Ry;
                    ksum -= kcur;
                }
                ep = e;

                par ^= 256u;
                sts64(base + par + hb, s0, s1);
            }
        }

        // ---------------- join (all 32 lanes participate in every shfl) --------
        u64 vf[8];
        lds4(base + par, vf);
        const float y0 = dot16(vf, Ca);            // fwd lanes: (E^T alpha_2047)_j
        const float y1 = dot16(vf, Cb);

        const float d0 = __shfl_sync(0xffffffffu, s0,   lane ^ 16);
        const float d1 = __shfl_sync(0xffffffffu, s1,   lane ^ 16);
        const int   kB = __shfl_sync(0xffffffffu, ksum, lane ^ 16);

        const int mju = mrowb[(size_t)HALF * mstride];
        const float2 e2k = erow2[(size_t)HALF * 8];
        // m=1: logZ = sum_j y_j * delta_{2048,j}
        // m=0: beta_2047 = beta_2048 -> sum_j alpha_j * delta_j / w_{2048,j}
        const float t0 = mju ? (y0 * d0) : (s0 * d0 * __expf(-e2k.x));
        const float t1 = mju ? (y1 * d1) : (s1 * d1 * __expf(-e2k.y));

        float z = t0 + t1;
        z += __shfl_xor_sync(0xffffffffu, z, 4, 8);
        z += __shfl_xor_sync(0xffffffffu, z, 2, 8);
        z += __shfl_xor_sync(0xffffffffu, z, 1, 8);
        if (dir == 0 && h == 0)
            g_fwd[row] = logf(z) + (float)(ksum + kB) * 0.6931471805599453f;
    }

    // Phase boundary: warp 1 sleeps here during the whole scan (BAR defer).
    __syncthreads();

    // ---------------- gold path score: one row per warp, post-scan ----------
    gold_row(blockIdx.x * 2 + warp, tags_b, tstride, mask_b, mstride,
             emissions, start_t, end_t, transitions, lane);

    // ---------------- last-block global reduction ----------------
    __syncthreads();
    if (threadIdx.x == 0) {
        __threadfence();
        const unsigned old = atomicAdd(&g_done, 1u);
        s_last = (old == NBLK - 1u) ? 1 : 0;
    }
    __syncthreads();
    if (s_last) {
        __threadfence();
        float a = 0.0f;
        for (int i = threadIdx.x; i < B_SZ; i += 64)
            a += g_fwd[i] - g_gold[i];
#pragma unroll
        for (int off = 16; off >= 1; off >>= 1)
            a += __shfl_xor_sync(0xffffffffu, a, off);
        __shared__ float wsum[2];
        if ((threadIdx.x & 31) == 0) wsum[threadIdx.x >> 5] = a;
        __syncthreads();
        if (threadIdx.x == 0) {
            out[0] = (wsum[0] + wsum[1]) * (1.0f / (float)B_SZ);
            g_done = 0;                      // reset for next graph replay
        }
    }
}

extern "C" void kernel_launch(void* const* d_in, const int* in_sizes, int n_in,
                              void* d_out, int out_size)
{
    (void)in_sizes; (void)n_in; (void)out_size;
    const float* emissions   = (const float*)d_in[0];
    const void*  tags        = d_in[1];
    const void*  mask        = d_in[2];
    const float* transitions = (const float*)d_in[3];
    const float* start_t     = (const float*)d_in[4];
    const float* end_t       = (const float*)d_in[5];

    crf_fused_kernel<<<NBLK, 64>>>(emissions, tags, mask, transitions,
                                   start_t, end_t, (float*)d_out);
}

// round 16
// speedup vs baseline: 1.5050x; 1.5050x over previous
#include <cuda_runtime.h>
#include <cstdint>
#include <math.h>

#define NT     16
#define S_LEN  4096
#define B_SZ   512
#define HALF   (S_LEN / 2)                 // 2048 iterations
#define CHUNK  8
#define NBLK   (B_SZ / 2)                  // 256 blocks, 2 rows each

typedef unsigned long long u64;

// Per-row partial results + completion counter (device globals: legal scratch).
__device__ float g_fwd[B_SZ];
__device__ float g_gold[B_SZ];
__device__ unsigned g_done = 0;

// ---- packed fp32x2 math ----
__device__ __forceinline__ u64 mul2(u64 a, u64 b) {
    u64 d; asm("mul.rn.f32x2 %0, %1, %2;" : "=l"(d) : "l"(a), "l"(b)); return d;
}
__device__ __forceinline__ u64 fma2(u64 a, u64 b, u64 c) {
    u64 d; asm("fma.rn.f32x2 %0, %1, %2, %3;" : "=l"(d) : "l"(a), "l"(b), "l"(c)); return d;
}
__device__ __forceinline__ u64 add2(u64 a, u64 b) {
    u64 d; asm("add.rn.f32x2 %0, %1, %2;" : "=l"(d) : "l"(a), "l"(b)); return d;
}
__device__ __forceinline__ u64 pack2(float lo, float hi) {
    u64 d; asm("mov.b64 %0, {%1, %2};" : "=l"(d) : "f"(lo), "f"(hi)); return d;
}
__device__ __forceinline__ void unpack2(u64 v, float& lo, float& hi) {
    asm("mov.b64 {%0, %1}, %2;" : "=f"(lo), "=f"(hi) : "l"(v));
}

__device__ __forceinline__ float dot16(const u64* v, const u64* c) {
    u64 p0 = mul2(v[0], c[0]);
    u64 p1 = mul2(v[1], c[1]);
    u64 p2 = mul2(v[2], c[2]);
    u64 p3 = mul2(v[3], c[3]);
    p0 = fma2(v[4], c[4], p0);
    p1 = fma2(v[5], c[5], p1);
    p2 = fma2(v[6], c[6], p2);
    p3 = fma2(v[7], c[7], p3);
    const u64 q0 = add2(p0, p1);
    const u64 q1 = add2(p2, p3);
    const u64 qq = add2(q0, q1);
    float lo, hi;
    unpack2(qq, lo, hi);
    return lo + hi;
}

// Butterfly all-gather within 8-lane stream: v[i] = pair(h ^ i).
// 3 rounds of u64 shfl_xor (offsets 1,2,4 stay inside the 8-lane group).
__device__ __forceinline__ void bfly_gather(float s0, float s1, u64* v) {
    v[0] = pack2(s0, s1);
    v[1] = __shfl_xor_sync(0xffffffffu, v[0], 1);
    v[2] = __shfl_xor_sync(0xffffffffu, v[0], 2);
    v[3] = __shfl_xor_sync(0xffffffffu, v[1], 2);
    v[4] = __shfl_xor_sync(0xffffffffu, v[0], 4);
    v[5] = __shfl_xor_sync(0xffffffffu, v[1], 4);
    v[6] = __shfl_xor_sync(0xffffffffu, v[2], 4);
    v[7] = __shfl_xor_sync(0xffffffffu, v[3], 4);
}

// Detect element strides (bytes) of tags/mask buffers (JAX dtype ambiguity).
__device__ __forceinline__ int detect_mask_stride(const unsigned char* mb) {
    return (mb[1] | mb[2] | mb[3]) ? 1 : 4;
}
__device__ __forceinline__ int detect_tag_stride(const void* tp) {
    const int* w = (const int*)tp;
    int nz = 0;
#pragma unroll
    for (int k = 0; k < 32; ++k) nz |= w[1 + 2 * k];
    return nz ? 4 : 8;
}

// One block = 64 threads = 2 warps, 2 batch rows.
//   warp 0: bidirectional scan, 4 streams of 8 lanes (register-butterfly transport):
//           q = lane>>3: dir = q>>1, r = q&1; lane owns components (2h, 2h+1).
//           fwd: alpha_t = w_t.(E^T alpha_{t-1});  bwd (delta): d_t = (E d_{t+1}).w_t
//   warp 1: gold path score for both rows (concurrent; proven free in R14).
__global__ void __launch_bounds__(64, 1) crf_fused_kernel(
    const float* __restrict__ emissions,          // [B, S, NT] f32
    const void*  __restrict__ tags_raw,           // [B, S] i32 or i64
    const void*  __restrict__ mask_raw,           // [B, S] u8 or i32 (bool)
    const float* __restrict__ transitions,        // [NT, NT] f32
    const float* __restrict__ start_t,            // [NT] f32
    const float* __restrict__ end_t,              // [NT] f32
    float* __restrict__ out)
{
    const int warp = threadIdx.x >> 5;
    const int lane = threadIdx.x & 31;

    const unsigned char* mask_b = (const unsigned char*)mask_raw;
    const unsigned char* tags_b = (const unsigned char*)tags_raw;
    const int mstride = detect_mask_stride(mask_b);
    const int tstride = detect_tag_stride(tags_raw);

    __shared__ int s_last;

    if (warp == 0) {
        const int q   = lane >> 3;                // stream id
        const int dir = q >> 1;                   // 0 fwd, 1 bwd
        const int r   = q & 1;                    // row within block
        const int h   = lane & 7;                 // owns tags 2h, 2h+1
        const int j0  = 2 * h, j1 = 2 * h + 1;
        const int row = blockIdx.x * 2 + r;
        const int sbl = lane & 24;                // stream base lane (holds pair 0)

        // dot constants permuted to butterfly arrival order: v[i] = pair(h^i).
        // fwd lane pairs with columns j0/j1 of expT; bwd with rows j0/j1.
        u64 Ca[8], Cb[8];
#pragma unroll
        for (int i = 0; i < 8; ++i) {
            const int g  = h ^ i;                 // pair index delivered in v[i]
            const int ta = 2 * g, tb = 2 * g + 1; // its two tag components
            const int a0 = dir ? (j0 * NT + ta) : (ta * NT + j0);
            const int a1 = dir ? (j0 * NT + tb) : (tb * NT + j0);
            const int b0 = dir ? (j1 * NT + ta) : (ta * NT + j1);
            const int b1 = dir ? (j1 * NT + tb) : (tb * NT + j1);
            Ca[i] = pack2(__expf(transitions[a0]), __expf(transitions[a1]));
            Cb[i] = pack2(__expf(transitions[b0]), __expf(transitions[b1]));
        }

        const float2* erow2 =
            reinterpret_cast<const float2*>(emissions + (size_t)row * S_LEN * NT) + h;
        const unsigned char* mrowb = mask_b + (size_t)row * S_LEN * mstride;
        const float dirf = dir ? 1.0f : 0.0f;

        // prologue prefetch. iteration i: fwd e_i, m_i; bwd e_{S-1-i}, m_{S-i}.
        float2 ebuf[CHUNK];
        int    mbuf[CHUNK];
#pragma unroll
        for (int p = 0; p < CHUNK; ++p) {
            const int et = dir ? (S_LEN - 1 - p) : p;
            const int mt = dir ? ((p == 0) ? S_LEN - 1 : S_LEN - p) : p;
            ebuf[p] = erow2[(size_t)et * 8];
            mbuf[p] = mrowb[(size_t)mt * mstride];
        }
        mbuf[0] = 0;                              // iteration 0 = init step

        // steady-state prefetch pointers (pointer-bump only; always in-bounds)
        const int estep = dir ? -8 : 8;           // float2 units per t
        const int mstep = dir ? -mstride : mstride;
        const float2* epf = erow2 + (dir ? (size_t)(S_LEN - 1 - CHUNK) * 8
                                         : (size_t)CHUNK * 8);
        const unsigned char* mpf = mrowb + (dir ? (size_t)(S_LEN - CHUNK) * mstride
                                                : (size_t)CHUNK * mstride);

        // init: fwd alpha_0 = exp(start + e_0); bwd d_{S-1} = exp(end + e_{S-1})
        const float base0 = dir ? end_t[j0] : start_t[j0];
        const float base1 = dir ? end_t[j1] : start_t[j1];
        float s0 = __expf(base0 + ebuf[0].x);
        float s1 = __expf(base1 + ebuf[0].y);
        float2 ep = ebuf[0];
        int    ksum = 0;

        for (int tb = 0; tb < HALF; tb += CHUNK) {
#pragma unroll
            for (int u = 0; u < CHUNK; ++u) {
                const float2 e = ebuf[u];
                const int    m = mbuf[u];

                // off-chain emission weights (e loaded CHUNK iterations ago)
                const float wx = __expf(e.x);
                const float wy = __expf(e.y);
                const unsigned pbx = __float_as_uint(wx) + 0x3f800000u;
                const unsigned pby = __float_as_uint(wy) + 0x3f800000u;
                // masked arm: fwd keep s (exp(0)); bwd s*exp(e_new - e_old)
                const float Rx = __expf((e.x - ep.x) * dirf);
                const float Ry = __expf((e.y - ep.y) * dirf);
                const float sRx = s0 * Rx;
                const float sRy = s1 * Ry;

                // pair-0 exponent broadcast (uniform scale across the stream);
                // issues immediately, overlaps the butterfly below
                const unsigned ub =
                    __shfl_sync(0xffffffffu, __float_as_uint(s0), sbl);

                // register butterfly all-gather (no smem round-trip)
                u64 v[8];
                bfly_gather(s0, s1, v);

                // prefetch (always in-bounds within the row)
                ebuf[u] = *epf;  epf += estep;
                mbuf[u] = *mpf;  mpf += mstep;

                // exponent fold: P = w * 2^-k from stream state[0]
                const int kcur = (int)((ub >> 23) & 0xffu) - 127;
                const unsigned msk = ub & 0x7f800000u;
                const float Px = __uint_as_float(pbx - msk);
                const float Py = __uint_as_float(pby - msk);

                // two independent packed trees
                const float accx = dot16(v, Ca);
                const float accy = dot16(v, Cb);

                s0    = m ? (accx * Px) : sRx;
                s1    = m ? (accy * Py) : sRy;
                ksum += m * kcur;
                ep    = e;
            }
        }

        // ---------------- join (all 32 lanes participate in every shfl) --------
        u64 vf[8];
        bfly_gather(s0, s1, vf);
        const float y0 = dot16(vf, Ca);            // fwd lanes: (E^T alpha_2047)_j
        const float y1 = dot16(vf, Cb);

        const float d0 = __shfl_sync(0xffffffffu, s0,   lane ^ 16);
        const float d1 = __shfl_sync(0xffffffffu, s1,   lane ^ 16);
        const int   kB = __shfl_sync(0xffffffffu, ksum, lane ^ 16);

        const int mju = mrowb[(size_t)HALF * mstride];
        const float2 e2k = erow2[(size_t)HALF * 8];
        // m=1: logZ = sum_j y_j * delta_{2048,j}
        // m=0: beta_2047 = beta_2048 -> sum_j alpha_j * delta_j / w_{2048,j}
        const float t0 = mju ? (y0 * d0) : (s0 * d0 * __expf(-e2k.x));
        const float t1 = mju ? (y1 * d1) : (s1 * d1 * __expf(-e2k.y));

        float z = t0 + t1;
        z += __shfl_xor_sync(0xffffffffu, z, 4, 8);
        z += __shfl_xor_sync(0xffffffffu, z, 2, 8);
        z += __shfl_xor_sync(0xffffffffu, z, 1, 8);
        if (dir == 0 && h == 0)
            g_fwd[row] = logf(z) + (float)(ksum + kB) * 0.6931471805599453f;
    } else {
        // ---------------- gold path score (concurrent, verbatim R14) ----------
        const int j   = lane & 15;
        const int row = blockIdx.x * 2 + (lane >> 4);
        const unsigned char* trow = tags_b + (size_t)row * S_LEN * tstride;
        const unsigned char* mrow = mask_b + (size_t)row * S_LEN * mstride;
        const float*         erow = emissions + (size_t)row * S_LEN * NT;

        float acc = 0.0f;
        int   cnt = 0;
        for (int t = j; t < S_LEN; t += 16) {
            const int tg = trow[(size_t)t * tstride];
            const int mm = mrow[(size_t)t * mstride];
            cnt += mm ? 1 : 0;
            if (t == 0) {
                acc += start_t[tg] + erow[tg];
            } else if (mm) {
                const int tpv = trow[(size_t)(t - 1) * tstride];
                acc += transitions[tpv * NT + tg] + erow[(size_t)t * NT + tg];
            }
        }
#pragma unroll
        for (int off = 8; off >= 1; off >>= 1) {
            acc += __shfl_xor_sync(0xffffffffu, acc, off, 16);
            cnt += __shfl_xor_sync(0xffffffffu, cnt, off, 16);
        }
        if (j == 0) {
            int last = cnt - 1;
            if (last < 0) last = 0;
            const int lt = trow[(size_t)last * tstride];
            g_gold[row] = acc + end_t[lt];
        }
    }

    // ---------------- last-block global reduction ----------------
    __syncthreads();
    if (threadIdx.x == 0) {
        __threadfence();
        const unsigned old = atomicAdd(&g_done, 1u);
        s_last = (old == NBLK - 1u) ? 1 : 0;
    }
    __syncthreads();
    if (s_last) {
        __threadfence();
        float a = 0.0f;
        for (int i = threadIdx.x; i < B_SZ; i += 64)
            a += g_fwd[i] - g_gold[i];
#pragma unroll
        for (int off = 16; off >= 1; off >>= 1)
            a += __shfl_xor_sync(0xffffffffu, a, off);
        __shared__ float wsum[2];
        if ((threadIdx.x & 31) == 0) wsum[threadIdx.x >> 5] = a;
        __syncthreads();
        if (threadIdx.x == 0) {
            out[0] = (wsum[0] + wsum[1]) * (1.0f / (float)B_SZ);
            g_done = 0;                      // reset for next graph replay
        }
    }
}

extern "C" void kernel_launch(void* const* d_in, const int* in_sizes, int n_in,
                              void* d_out, int out_size)
{
    (void)in_sizes; (void)n_in; (void)out_size;
    const float* emissions   = (const float*)d_in[0];
    const void*  tags        = d_in[1];
    const void*  mask        = d_in[2];
    const float* transitions = (const float*)d_in[3];
    const float* start_t     = (const float*)d_in[4];
    const float* end_t       = (const float*)d_in[5];

    crf_fused_kernel<<<NBLK, 64>>>(emissions, tags, mask, transitions,
                                   start_t, end_t, (float*)d_out);
}